// round 11
// baseline (speedup 1.0000x reference)
#include <cuda_runtime.h>
#include <cuda_bf16.h>

// RipsLayer: out[t] = ||X[i_t] - X[j_t]||, t in [0, 16384), D=3.
//
// FINAL (converged; champion reproduced 4x: 6.208, 6.208, 6.144 us within
// the [6.11, 6.27] noise band). The reference materializes the dense
// 8192x8192 distance matrix (256 MB, ~67M sqrt) and gathers 16384 entries;
// this kernel computes only the gathered entries (~0.6 MB traffic, 2-hop
// chain idx -> 12 gathers): ~41,000x less memory traffic.
//
// Session findings (11 benches, 6 configs):
//  - All configs with >=128-block SM coverage tie at a launch-overhead floor
//    (+/-2 timer quanta run-to-run noise). Only 32-block coverage loses
//    (6.50us): latency hiding needs SM spread, not per-thread MLP.
//  - Throughput metrics all idle (DRAM 0.6%, issue 2%, fma 0.2%): the kernel
//    is launch-bound; warm-replay kernel work is <1us, the rest is fixed
//    graph-replay/launch cost outside kernel-source control.
//  - Rejected with evidence: >2 outputs/thread (coverage loss), smem staging
//    of X (12 MB broadcast vs 96 KB L2-resident table), float4 row gathers
//    (12 B rows only 4 B-aligned), repack pre-pass (+1 launch > savings),
//    fast-math/store hints (sub-quantum at 2% issue).
//
// Champion: 256 CTAs x 32 threads, 2 outputs/thread, one coalesced int4 idx
// load, byte-offset addressing, 12 front-batched gathers, float2 store.
//
// Inputs (metadata order):
//   d_in[0] = X       float32 [8192, 3]
//   d_in[1] = indices int32   [8192, 2, 2] -> flattened (i,j) per output
// Output:
//   d_out   = dgm     float32 [8192, 2]    (16384 floats)

__global__ void __launch_bounds__(32, 32)
rips_gather_dist2_kernel(const float* __restrict__ X,
                         const int4* __restrict__ idx4,
                         float2* __restrict__ out2) {
    int t = blockIdx.x * 32 + threadIdx.x;   // 8192 threads exactly

    int4 p = idx4[t];                        // (i0, j0, i1, j1)

    const char* Xb = (const char*)X;
    // row byte offset = idx * 12 (LEA-friendly, avoids IMAD chains)
    const float* a0 = (const float*)(Xb + (size_t)p.x * 12u);
    const float* b0 = (const float*)(Xb + (size_t)p.y * 12u);
    const float* a1 = (const float*)(Xb + (size_t)p.z * 12u);
    const float* b1 = (const float*)(Xb + (size_t)p.w * 12u);

    // 12 independent gathers, all issued before any consumer.
    float a0x = __ldg(a0 + 0), a0y = __ldg(a0 + 1), a0z = __ldg(a0 + 2);
    float b0x = __ldg(b0 + 0), b0y = __ldg(b0 + 1), b0z = __ldg(b0 + 2);
    float a1x = __ldg(a1 + 0), a1y = __ldg(a1 + 1), a1z = __ldg(a1 + 2);
    float b1x = __ldg(b1 + 0), b1y = __ldg(b1 + 1), b1z = __ldg(b1 + 2);

    float d0x = a0x - b0x, d0y = a0y - b0y, d0z = a0z - b0z;
    float d1x = a1x - b1x, d1y = a1y - b1y, d1z = a1z - b1z;

    float r0 = sqrtf(fmaf(d0x, d0x, fmaf(d0y, d0y, d0z * d0z)));
    float r1 = sqrtf(fmaf(d1x, d1x, fmaf(d1y, d1y, d1z * d1z)));

    out2[t] = make_float2(r0, r1);
}

extern "C" void kernel_launch(void* const* d_in, const int* in_sizes, int n_in,
                              void* d_out, int out_size) {
    const float* X    = (const float*)d_in[0];
    const int4*  idx4 = (const int4*)d_in[1];   // one int4 = 2 (i,j) pairs
    float2*      out2 = (float2*)d_out;

    // 8192 threads exactly: 256 blocks x 32 threads, all SMs covered.
    rips_gather_dist2_kernel<<<256, 32>>>(X, idx4, out2);
}

// round 12
// speedup vs baseline: 1.0105x; 1.0105x over previous
#include <cuda_runtime.h>
#include <cuda_bf16.h>

// RipsLayer: out[t] = ||X[i_t] - X[j_t]||, t in [0, 16384), D=3.
//
// FINAL (converged; champion reproduced 5x: 6.208, 6.208, 6.144, 6.176 us,
// noise band [6.11, 6.27]). The reference materializes the dense 8192x8192
// distance matrix (256 MB, ~67M sqrt) and gathers 16384 entries; this kernel
// computes only the gathered entries (~0.6 MB traffic, 2-hop chain
// idx -> 12 gathers): ~41,000x less memory traffic.
//
// Session findings (12 benches, 6 configs):
//  - All configs with >=128-block SM coverage tie at a launch-overhead floor
//    (+/-2 timer quanta run-to-run noise). Only 32-block coverage loses
//    (6.50us): latency hiding needs SM spread, not per-thread MLP.
//  - Throughput metrics all idle (DRAM 0.6%, issue 2%, fma 0.2%): the kernel
//    is launch-bound; warm-replay kernel work is <1us, the rest is fixed
//    graph-replay/launch cost outside kernel-source control.
//  - Rejected with evidence: >2 outputs/thread (coverage loss), smem staging
//    of X (12 MB broadcast vs 96 KB L2-resident table), float4 row gathers
//    (12 B rows only 4 B-aligned), repack pre-pass (+1 launch > savings),
//    fast-math/store hints (sub-quantum at 2% issue).
//
// Champion: 256 CTAs x 32 threads, 2 outputs/thread, one coalesced int4 idx
// load, byte-offset addressing, 12 front-batched gathers, float2 store.
//
// Inputs (metadata order):
//   d_in[0] = X       float32 [8192, 3]
//   d_in[1] = indices int32   [8192, 2, 2] -> flattened (i,j) per output
// Output:
//   d_out   = dgm     float32 [8192, 2]    (16384 floats)

__global__ void __launch_bounds__(32, 32)
rips_gather_dist2_kernel(const float* __restrict__ X,
                         const int4* __restrict__ idx4,
                         float2* __restrict__ out2) {
    int t = blockIdx.x * 32 + threadIdx.x;   // 8192 threads exactly

    int4 p = idx4[t];                        // (i0, j0, i1, j1)

    const char* Xb = (const char*)X;
    // row byte offset = idx * 12 (LEA-friendly, avoids IMAD chains)
    const float* a0 = (const float*)(Xb + (size_t)p.x * 12u);
    const float* b0 = (const float*)(Xb + (size_t)p.y * 12u);
    const float* a1 = (const float*)(Xb + (size_t)p.z * 12u);
    const float* b1 = (const float*)(Xb + (size_t)p.w * 12u);

    // 12 independent gathers, all issued before any consumer.
    float a0x = __ldg(a0 + 0), a0y = __ldg(a0 + 1), a0z = __ldg(a0 + 2);
    float b0x = __ldg(b0 + 0), b0y = __ldg(b0 + 1), b0z = __ldg(b0 + 2);
    float a1x = __ldg(a1 + 0), a1y = __ldg(a1 + 1), a1z = __ldg(a1 + 2);
    float b1x = __ldg(b1 + 0), b1y = __ldg(b1 + 1), b1z = __ldg(b1 + 2);

    float d0x = a0x - b0x, d0y = a0y - b0y, d0z = a0z - b0z;
    float d1x = a1x - b1x, d1y = a1y - b1y, d1z = a1z - b1z;

    float r0 = sqrtf(fmaf(d0x, d0x, fmaf(d0y, d0y, d0z * d0z)));
    float r1 = sqrtf(fmaf(d1x, d1x, fmaf(d1y, d1y, d1z * d1z)));

    out2[t] = make_float2(r0, r1);
}

extern "C" void kernel_launch(void* const* d_in, const int* in_sizes, int n_in,
                              void* d_out, int out_size) {
    const float* X    = (const float*)d_in[0];
    const int4*  idx4 = (const int4*)d_in[1];   // one int4 = 2 (i,j) pairs
    float2*      out2 = (float2*)d_out;

    // 8192 threads exactly: 256 blocks x 32 threads, all SMs covered.
    rips_gather_dist2_kernel<<<256, 32>>>(X, idx4, out2);
}